// round 10
// baseline (speedup 1.0000x reference)
#include <cuda_runtime.h>
#include <cuda_fp16.h>
#include <cstdint>

#define NB 4096
#define NT 32               // 32x32 grid of 128x128 tiles
#define NITEMS 1056         // two 128x64 half-tiles per upper-triangle tile
#define FMA_STOP 992        // fma CTAs stop claiming near the tail

// ---------------- device scratch (static: no allocation allowed) ----------------
// C row (256 fp16, 512B): [x | -2m | 1/v | m/v], x = v + m^2
// "D" row = C rotated by 128 cols; K-chunk c of D = chunk 1-c of C (256B chunks).
__device__ __half g_C[(size_t)NB * 256];
__device__ float  g_A8[NB];    // 0.125*a_i - 8
__device__ float  g_P8[NB];    // 0.125*p_i
__device__ float  g_Q[NB];     // 1/(p_i + 1e-8)
__device__ double g_pos, g_neg;
__device__ unsigned g_arrive = 0, g_done = 0, g_ticket = 0;
__device__ volatile unsigned g_release = 0;

static __device__ __forceinline__ uint32_t smem_u32(const void* p) {
    uint32_t a;
    asm("{ .reg .u64 t; cvta.to.shared.u64 t, %1; cvt.u32.u64 %0, t; }" : "=r"(a) : "l"(p));
    return a;
}
static __device__ __forceinline__ float frcp(float x) {
    float r; asm("rcp.approx.f32 %0, %1;" : "=f"(r) : "f"(x)); return r;
}
static __device__ __forceinline__ float ftanh(float x) {
    float r; asm("tanh.approx.f32 %0, %1;" : "=f"(r) : "f"(x)); return r;
}
static __device__ __forceinline__ void cpa16(uint32_t dst, const void* src) {
    asm volatile("cp.async.ca.shared.global [%0], [%1], 16;" :: "r"(dst), "l"(src));
}

// smem: A chunk 128x128 fp16 (32KB, XOR-swizzled 16B chunks, pitch 256B),
//       B chunk 64x128 fp16 (16KB), params, scratch
#define AS_OFF 0
#define BS_OFF 32768
#define PAR_OFF 49152
#define RED_OFF 52224
#define SMEM_BYTES 52288

// ---- stage one K=128 chunk: A rows [Ibase,+128) chunk c, B rows [Jbase,+64) chunk 1-c
static __device__ __forceinline__ void stage_chunk(
    uint32_t sbase, const char* baseI, const char* baseJ, int c, int tid)
{
    int pa = c * 256, pb = 256 - c * 256;
    #pragma unroll
    for (int p = 0; p < 16; p++) {
        int idx = tid + p * 128, r = idx >> 4, c16 = idx & 15;
        cpa16(sbase + AS_OFF + r * 256 + ((c16 ^ (r & 7)) << 4),
              baseI + r * 512 + pa + c16 * 16);
    }
    #pragma unroll
    for (int p = 0; p < 8; p++) {
        int idx = tid + p * 128, r = idx >> 4, c16 = idx & 15;
        cpa16(sbase + BS_OFF + r * 256 + ((c16 ^ (r & 7)) << 4),
              baseJ + r * 512 + pb + c16 * 16);
    }
    asm volatile("cp.async.commit_group;" ::: "memory");
}

// ---- tensor: one K=128 chunk of the 128x64 GEMM (warp tile 64x32) ----
static __device__ __forceinline__ void gemm_chunk(
    uint32_t csA, uint32_t csB, int lane, int warp_m, int warp_n,
    uint32_t (&acc)[4][4][2])
{
    #pragma unroll
    for (int s = 0; s < 8; s++) {
        uint32_t af[4][4];
        #pragma unroll
        for (int mi = 0; mi < 4; mi++) {
            int r = warp_m * 64 + mi * 16 + (lane & 15);
            int c16 = 2 * s + (lane >> 4);
            uint32_t addr = csA + r * 256 + ((c16 ^ (r & 7)) << 4);
            asm volatile("ldmatrix.sync.aligned.m8n8.x4.shared.b16 {%0,%1,%2,%3}, [%4];"
                         : "=r"(af[mi][0]), "=r"(af[mi][1]), "=r"(af[mi][2]), "=r"(af[mi][3])
                         : "r"(addr));
        }
        #pragma unroll
        for (int ni = 0; ni < 4; ni++) {
            int r = warp_n * 32 + ni * 8 + (lane & 7);
            int c16 = 2 * s + ((lane >> 3) & 1);
            uint32_t addr = csB + r * 256 + ((c16 ^ (r & 7)) << 4);
            uint32_t b0, b1;
            asm volatile("ldmatrix.sync.aligned.m8n8.x2.shared.b16 {%0,%1}, [%2];"
                         : "=r"(b0), "=r"(b1) : "r"(addr));
            #pragma unroll
            for (int mi = 0; mi < 4; mi++) {
                asm volatile(
                    "mma.sync.aligned.m16n8k16.row.col.f16.f16.f16.f16 "
                    "{%0,%1}, {%2,%3,%4,%5}, {%6,%7}, {%0,%1};"
                    : "+r"(acc[mi][ni][0]), "+r"(acc[mi][ni][1])
                    : "r"(af[mi][0]), "r"(af[mi][1]), "r"(af[mi][2]), "r"(af[mi][3]),
                      "r"(b0), "r"(b1));
            }
        }
    }
}

// ---- fma: one K=128 chunk; thread (tr,tc) owns 8x8 outputs; half2 accumulators ----
static __device__ __forceinline__ void fma_chunk(
    const char* sm, int tr, int tc, uint32_t (&acc)[8][8])
{
    #pragma unroll 8
    for (int k2 = 0; k2 < 64; k2++) {
        int c16 = k2 >> 2, b4 = (k2 & 3) << 2;
        uint32_t a[8], b[8];
        #pragma unroll
        for (int i = 0; i < 8; i++) {
            int r = tr * 8 + i;
            a[i] = *(const uint32_t*)(sm + AS_OFF + r * 256 + ((c16 ^ (r & 7)) << 4) + b4);
        }
        #pragma unroll
        for (int j = 0; j < 8; j++) {
            int cc = tc * 8 + j;
            b[j] = *(const uint32_t*)(sm + BS_OFF + cc * 256 + ((c16 ^ (cc & 7)) << 4) + b4);
        }
        #pragma unroll
        for (int i = 0; i < 8; i++) {
            __half2 ai = *(__half2*)&a[i];
            #pragma unroll
            for (int j = 0; j < 8; j++) {
                __half2 t = *(__half2*)&acc[i][j];
                t = __hfma2(ai, *(__half2*)&b[j], t);
                acc[i][j] = *(uint32_t*)&t;
            }
        }
    }
}

static __device__ __forceinline__ void decode_item(unsigned t, int& I, int& J, int& half) {
    int ft = (int)(t >> 1); half = (int)(t & 1); I = 0;
    while (ft >= NT - I) { ft -= NT - I; I++; }
    J = I + ft;
}

__global__ void __launch_bounds__(128, 4) mega_kernel(
    const float* __restrict__ mu, const float* __restrict__ var,
    const int* __restrict__ labels, float* __restrict__ out)
{
    extern __shared__ char smem[];
    uint32_t sbase = smem_u32(smem);
    int tid = threadIdx.x, lane = tid & 31, wid = tid >> 5;

    // ================= phase 0: prep =================
    for (int row0 = blockIdx.x * 8; row0 < NB; row0 += gridDim.x * 8) {
        int row = row0 + (tid >> 4), l16 = tid & 15;
        float4 m4 = ((const float4*)(mu  + (size_t)row * 64))[l16];
        float4 v4 = ((const float4*)(var + (size_t)row * 64))[l16];
        float m[4] = {m4.x, m4.y, m4.z, m4.w};
        float v[4] = {v4.x, v4.y, v4.z, v4.w};
        float x[4], n2m[4], iv[4], w[4];
        float pv = 1.0f, av = 0.0f;
        #pragma unroll
        for (int d = 0; d < 4; d++) {
            iv[d]  = frcp(v[d]);
            x[d]   = v[d] + m[d] * m[d];
            n2m[d] = -2.0f * m[d];
            w[d]   = m[d] * iv[d];
            pv *= v[d];
            av = fmaf(m[d] * m[d], iv[d], av);
        }
        uint2* crow = (uint2*)(g_C + (size_t)row * 256);
        const float* blocks[4] = {x, n2m, iv, w};
        #pragma unroll
        for (int b = 0; b < 4; b++) {
            const float* s = blocks[b];
            __half2 h2[2] = {__floats2half2_rn(s[0], s[1]), __floats2half2_rn(s[2], s[3])};
            crow[b * 16 + l16] = *(uint2*)h2;
        }
        #pragma unroll
        for (int off = 1; off < 16; off <<= 1) {
            pv *= __shfl_xor_sync(0xffffffffu, pv, off);
            av += __shfl_xor_sync(0xffffffffu, av, off);
        }
        if (l16 == 0) {
            g_A8[row] = 0.125f * av - 8.0f;
            g_P8[row] = 0.125f * pv;
            g_Q[row]  = frcp(pv + 1e-8f);
        }
    }

    // ================= device-wide barrier =================
    __syncthreads();
    if (tid == 0) {
        unsigned target = g_release + 1;
        __threadfence();
        unsigned a = atomicAdd(&g_arrive, 1);
        if (a == gridDim.x - 1) {
            g_arrive = 0;
            g_pos = 0.0; g_neg = 0.0;
            g_ticket = gridDim.x;
            __threadfence();
            atomicAdd((unsigned*)&g_release, 1);
        } else {
            while (g_release < target) __nanosleep(64);
        }
        __threadfence();
    }
    __syncthreads();

    // ================= phase 1: half-tile (128x64) work loop =================
    float* spAI = (float*)(smem + PAR_OFF);
    float* spPI = spAI + 128;
    float* spQI = spPI + 128;
    int*   spLI = (int*)(spQI + 128);
    float* spAJ = (float*)(spLI + 128);   // 64 entries
    float* spPJ = spAJ + 64;
    float* spQJ = spPJ + 64;
    int*   spLJ = (int*)(spQJ + 64);
    float* red  = (float*)(smem + RED_OFF);
    unsigned* tick_s = (unsigned*)(red + 8);

    uint32_t csA = sbase + AS_OFF, csB = sbase + BS_OFF;
    const bool isFma = (blockIdx.x < 148);
    int warp_m = wid & 1, warp_n = wid >> 1;
    int tr = tid >> 3, tc = tid & 7;     // fma thread grid 16x8
    float pos = 0.0f, neg = 0.0f;
    unsigned t = blockIdx.x;

    while (t < NITEMS) {
        int I, J, half;
        decode_item(t, I, J, half);
        int Ibase = I * 128, Jbase = J * 128 + half * 64;
        const char* baseI = (const char*)g_C + (size_t)Ibase * 512;
        const char* baseJ = (const char*)g_C + (size_t)Jbase * 512;
        const bool diag = (I == J);

        __syncthreads();   // previous item's epilogue done with smem

        stage_chunk(sbase, baseI, baseJ, 0, tid);
        spAI[tid] = g_A8[Ibase + tid];
        spPI[tid] = g_P8[Ibase + tid];
        spQI[tid] = g_Q[Ibase + tid];
        spLI[tid] = labels[Ibase + tid];
        if (tid < 64) {
            spAJ[tid] = g_A8[Jbase + tid];
            spPJ[tid] = g_P8[Jbase + tid];
            spQJ[tid] = g_Q[Jbase + tid];
            spLJ[tid] = labels[Jbase + tid];
        }
        asm volatile("cp.async.wait_group 0;" ::: "memory");
        __syncthreads();

        if (!isFma) {
            // =========== tensor path ===========
            uint32_t acc[4][4][2];
            #pragma unroll
            for (int mi = 0; mi < 4; mi++)
                #pragma unroll
                for (int ni = 0; ni < 4; ni++) { acc[mi][ni][0] = 0u; acc[mi][ni][1] = 0u; }

            gemm_chunk(csA, csB, lane, warp_m, warp_n, acc);
            __syncthreads();
            stage_chunk(sbase, baseI, baseJ, 1, tid);
            if (tid == 0) {
                unsigned nt = atomicAdd(&g_ticket, 1);
                *tick_s = nt;
            }
            asm volatile("cp.async.wait_group 0;" ::: "memory");
            __syncthreads();
            gemm_chunk(csA, csB, lane, warp_m, warp_n, acc);

            #pragma unroll
            for (int mi = 0; mi < 4; mi++) {
                #pragma unroll
                for (int k = 0; k < 2; k++) {
                    int r = warp_m * 64 + mi * 16 + (lane >> 2) + k * 8;
                    float RA = spAI[r], RP = spPI[r], RQ = spQI[r];
                    int   RL = spLI[r];
                    #pragma unroll
                    for (int ni = 0; ni < 4; ni++) {
                        __half2 hv = *reinterpret_cast<__half2*>(&acc[mi][ni][k]);
                        float2 f = __half22float2(hv);
                        int c0 = warp_n * 32 + ni * 8 + (lane & 3) * 2;
                        #pragma unroll
                        for (int e = 0; e < 2; e++) {
                            int c = c0 + e;
                            float vv = e ? f.y : f.x;
                            float s = fmaf(vv, 0.125f, RA);
                            s += spAJ[c];
                            s = fmaf(RP, spQJ[c], s);
                            s = fmaf(spPJ[c], RQ, s);
                            float sg = fmaf(ftanh(s), 0.5f, 0.5f);
                            bool count = (!diag) || (half * 64 + c > r);
                            bool same  = (RL == spLJ[c]);
                            if (count) {
                                pos += same ? sg : 0.0f;
                                neg += same ? 0.0f : sg;
                            }
                        }
                    }
                }
            }
        } else {
            // =========== HFMA2 path: 8x8 register-blocked ===========
            uint32_t acc[8][8];
            #pragma unroll
            for (int i = 0; i < 8; i++)
                #pragma unroll
                for (int j = 0; j < 8; j++) acc[i][j] = 0u;

            fma_chunk(smem, tr, tc, acc);
            __syncthreads();
            stage_chunk(sbase, baseI, baseJ, 1, tid);
            if (tid == 0) {
                unsigned nt;
                if (g_ticket >= FMA_STOP) nt = NITEMS;
                else nt = atomicAdd(&g_ticket, 1);
                *tick_s = nt;
            }
            asm volatile("cp.async.wait_group 0;" ::: "memory");
            __syncthreads();
            fma_chunk(smem, tr, tc, acc);

            #pragma unroll
            for (int i = 0; i < 8; i++) {
                int r = tr * 8 + i;
                float RA = spAI[r], RP = spPI[r], RQ = spQI[r];
                int   RL = spLI[r];
                #pragma unroll
                for (int j = 0; j < 8; j++) {
                    int c = tc * 8 + j;
                    float2 f = __half22float2(*(__half2*)&acc[i][j]);
                    float vv = f.x + f.y;
                    float s = fmaf(vv, 0.125f, RA);
                    s += spAJ[c];
                    s = fmaf(RP, spQJ[c], s);
                    s = fmaf(spPJ[c], RQ, s);
                    float sg = fmaf(ftanh(s), 0.5f, 0.5f);
                    bool count = (!diag) || (half * 64 + c > r);
                    bool same  = (RL == spLJ[c]);
                    if (count) {
                        pos += same ? sg : 0.0f;
                        neg += same ? 0.0f : sg;
                    }
                }
            }
        }

        t = *tick_s;   // written before the pre-chunk1 sync
    }

    // ================= final reduce + output by last CTA =================
    #pragma unroll
    for (int off = 16; off; off >>= 1) {
        pos += __shfl_xor_sync(0xffffffffu, pos, off);
        neg += __shfl_xor_sync(0xffffffffu, neg, off);
    }
    __syncthreads();
    if (lane == 0) { red[wid] = pos; red[4 + wid] = neg; }
    __syncthreads();
    if (tid == 0) {
        double P = 0.0, Nn = 0.0;
        #pragma unroll
        for (int w = 0; w < 4; w++) { P += (double)red[w]; Nn += (double)red[4 + w]; }
        atomicAdd(&g_pos, P);
        atomicAdd(&g_neg, Nn);
        __threadfence();
        unsigned d = atomicAdd(&g_done, 1);
        if (d == gridDim.x - 1) {
            double TP = 2.0 * atomicAdd(&g_pos, 0.0);
            double TN = 2.0 * atomicAdd(&g_neg, 0.0);
            const double inv = 1.0 / ((double)NB * (double)NB);
            out[0] = (float)(TP * inv);
            out[1] = (float)(TN * inv);
            out[2] = (float)TP;
            out[3] = (float)TN;
            g_done = 0;
        }
    }
}

// ---------------- launcher ----------------
extern "C" void kernel_launch(void* const* d_in, const int* in_sizes, int n_in,
                              void* d_out, int out_size) {
    (void)in_sizes; (void)n_in; (void)out_size;
    const float* mu     = (const float*)d_in[0];
    const float* var    = (const float*)d_in[1];
    const int*   labels = (const int*)d_in[2];
    float* out = (float*)d_out;

    cudaFuncSetAttribute(mega_kernel, cudaFuncAttributeMaxDynamicSharedMemorySize,
                         SMEM_BYTES);
    int occ = 0, sms = 0, dev = 0;
    cudaGetDevice(&dev);
    cudaOccupancyMaxActiveBlocksPerMultiprocessor(&occ, mega_kernel, 128, SMEM_BYTES);
    cudaDeviceGetAttribute(&sms, cudaDevAttrMultiProcessorCount, dev);
    int grid = occ * sms;
    if (grid > NITEMS) grid = NITEMS;
    if (grid < 1) grid = 1;

    mega_kernel<<<grid, 128, SMEM_BYTES>>>(mu, var, labels, out);
}

// round 12
// speedup vs baseline: 2.1763x; 2.1763x over previous
#include <cuda_runtime.h>
#include <cuda_fp16.h>
#include <cstdint>

#define NB 4096
#define NT 32               // 32x32 grid of 128x128 tiles
#define NTILES 528          // upper-triangle tiles

// ---------------- device scratch (static: no allocation allowed) ----------------
// C row (256 fp16, 512B): [x | -2m | 1/v | m/v], x = v + m^2
// "D" row = C rotated by 128 cols; 64-wide K-chunk c of D = chunk (c+2)&3 of C.
__device__ __half g_C[(size_t)NB * 256];
__device__ float  g_A8[NB];    // 0.125*a_i - 8
__device__ float  g_P8[NB];    // 0.125*p_i
__device__ float  g_Q[NB];     // 1/(p_i + 1e-8)
__device__ double g_pos, g_neg;
__device__ unsigned g_arrive = 0, g_done = 0;
__device__ volatile unsigned g_release = 0;

static __device__ __forceinline__ uint32_t smem_u32(const void* p) {
    uint32_t a;
    asm("{ .reg .u64 t; cvta.to.shared.u64 t, %1; cvt.u32.u64 %0, t; }" : "=r"(a) : "l"(p));
    return a;
}
static __device__ __forceinline__ float frcp(float x) {
    float r; asm("rcp.approx.f32 %0, %1;" : "=f"(r) : "f"(x)); return r;
}
static __device__ __forceinline__ float ftanh(float x) {
    float r; asm("tanh.approx.f32 %0, %1;" : "=f"(r) : "f"(x)); return r;
}
static __device__ __forceinline__ void cpa16(uint32_t dst, const void* src) {
    asm volatile("cp.async.ca.shared.global [%0], [%1], 16;" :: "r"(dst), "l"(src));
}

// smem: A chunk 128 rows x 64 K (128B/row, XOR-swizzled 16B chunks) = 16KB
//       B chunk 128 rows x 64 K = 16KB, params 4KB, reduce scratch
#define AS_OFF 0
#define BS_OFF 16384
#define PAR_OFF 32768
#define RED_OFF 36864
#define SMEM_BYTES 36928

// ---- stage one 64-wide K chunk: A = C(I) chunk c, B = C(J) chunk (c+2)&3 ----
static __device__ __forceinline__ void stage_chunk(
    uint32_t sbase, const char* baseI, const char* baseJ, int c, int tid)
{
    int pa = c * 128, pb = ((c + 2) & 3) * 128;
    #pragma unroll
    for (int p = 0; p < 8; p++) {
        int idx = tid + p * 128, r = idx >> 3, c16 = idx & 7;
        cpa16(sbase + AS_OFF + r * 128 + ((c16 ^ (r & 7)) << 4),
              baseI + r * 512 + pa + c16 * 16);
    }
    #pragma unroll
    for (int p = 0; p < 8; p++) {
        int idx = tid + p * 128, r = idx >> 3, c16 = idx & 7;
        cpa16(sbase + BS_OFF + r * 128 + ((c16 ^ (r & 7)) << 4),
              baseJ + r * 512 + pb + c16 * 16);
    }
    asm volatile("cp.async.commit_group;" ::: "memory");
}

// ---- one 64-wide K chunk of the 128x128 GEMM; warp tile 64x64 (2x2 warp grid) ----
static __device__ __forceinline__ void gemm_chunk(
    uint32_t csA, uint32_t csB, int lane, int warp_m, int warp_n,
    uint32_t (&acc)[4][8][2])
{
    #pragma unroll
    for (int s = 0; s < 4; s++) {
        uint32_t af[4][4];
        #pragma unroll
        for (int mi = 0; mi < 4; mi++) {
            int r = warp_m * 64 + mi * 16 + (lane & 15);
            int c16 = 2 * s + (lane >> 4);
            uint32_t addr = csA + r * 128 + ((c16 ^ (r & 7)) << 4);
            asm volatile("ldmatrix.sync.aligned.m8n8.x4.shared.b16 {%0,%1,%2,%3}, [%4];"
                         : "=r"(af[mi][0]), "=r"(af[mi][1]), "=r"(af[mi][2]), "=r"(af[mi][3])
                         : "r"(addr));
        }
        #pragma unroll
        for (int ni = 0; ni < 8; ni++) {
            int r = warp_n * 64 + ni * 8 + (lane & 7);
            int c16 = 2 * s + ((lane >> 3) & 1);
            uint32_t addr = csB + r * 128 + ((c16 ^ (r & 7)) << 4);
            uint32_t b0, b1;
            asm volatile("ldmatrix.sync.aligned.m8n8.x2.shared.b16 {%0,%1}, [%2];"
                         : "=r"(b0), "=r"(b1) : "r"(addr));
            #pragma unroll
            for (int mi = 0; mi < 4; mi++) {
                asm volatile(
                    "mma.sync.aligned.m16n8k16.row.col.f16.f16.f16.f16 "
                    "{%0,%1}, {%2,%3,%4,%5}, {%6,%7}, {%0,%1};"
                    : "+r"(acc[mi][ni][0]), "+r"(acc[mi][ni][1])
                    : "r"(af[mi][0]), "r"(af[mi][1]), "r"(af[mi][2]), "r"(af[mi][3]),
                      "r"(b0), "r"(b1));
            }
        }
    }
}

static __device__ __forceinline__ void decode_tile(int ft, int& I, int& J) {
    I = 0;
    while (ft >= NT - I) { ft -= NT - I; I++; }
    J = I + ft;
}

__global__ void __launch_bounds__(128, 4) mega_kernel(
    const float* __restrict__ mu, const float* __restrict__ var,
    const int* __restrict__ labels, float* __restrict__ out)
{
    extern __shared__ char smem[];
    uint32_t sbase = smem_u32(smem);
    int tid = threadIdx.x, lane = tid & 31, wid = tid >> 5;

    // ================= phase 0: prep =================
    for (int row0 = blockIdx.x * 8; row0 < NB; row0 += gridDim.x * 8) {
        int row = row0 + (tid >> 4), l16 = tid & 15;
        float4 m4 = ((const float4*)(mu  + (size_t)row * 64))[l16];
        float4 v4 = ((const float4*)(var + (size_t)row * 64))[l16];
        float m[4] = {m4.x, m4.y, m4.z, m4.w};
        float v[4] = {v4.x, v4.y, v4.z, v4.w};
        float x[4], n2m[4], iv[4], w[4];
        float pv = 1.0f, av = 0.0f;
        #pragma unroll
        for (int d = 0; d < 4; d++) {
            iv[d]  = frcp(v[d]);
            x[d]   = v[d] + m[d] * m[d];
            n2m[d] = -2.0f * m[d];
            w[d]   = m[d] * iv[d];
            pv *= v[d];
            av = fmaf(m[d] * m[d], iv[d], av);
        }
        uint2* crow = (uint2*)(g_C + (size_t)row * 256);
        const float* blocks[4] = {x, n2m, iv, w};
        #pragma unroll
        for (int b = 0; b < 4; b++) {
            const float* s = blocks[b];
            __half2 h2[2] = {__floats2half2_rn(s[0], s[1]), __floats2half2_rn(s[2], s[3])};
            crow[b * 16 + l16] = *(uint2*)h2;
        }
        #pragma unroll
        for (int off = 1; off < 16; off <<= 1) {
            pv *= __shfl_xor_sync(0xffffffffu, pv, off);
            av += __shfl_xor_sync(0xffffffffu, av, off);
        }
        if (l16 == 0) {
            g_A8[row] = 0.125f * av - 8.0f;
            g_P8[row] = 0.125f * pv;
            g_Q[row]  = frcp(pv + 1e-8f);
        }
    }

    // ================= device-wide barrier (all CTAs resident) =================
    __syncthreads();
    if (tid == 0) {
        unsigned target = g_release + 1;
        __threadfence();
        unsigned a = atomicAdd(&g_arrive, 1);
        if (a == gridDim.x - 1) {
            g_arrive = 0;
            g_pos = 0.0; g_neg = 0.0;
            __threadfence();
            atomicAdd((unsigned*)&g_release, 1);
        } else {
            while (g_release < target) __nanosleep(64);
        }
        __threadfence();
    }
    __syncthreads();

    // ================= phase 1: static full-tile loop (single wave) =================
    float* spAI = (float*)(smem + PAR_OFF);
    float* spPI = spAI + 128;
    float* spQI = spPI + 128;
    int*   spLI = (int*)(spQI + 128);
    float* spAJ = (float*)(spLI + 128);
    float* spPJ = spAJ + 128;
    float* spQJ = spPJ + 128;
    int*   spLJ = (int*)(spQJ + 128);
    float* red  = (float*)(smem + RED_OFF);

    uint32_t csA = sbase + AS_OFF, csB = sbase + BS_OFF;
    int warp_m = wid & 1, warp_n = wid >> 1;
    float pos = 0.0f, neg = 0.0f;

    for (int t = blockIdx.x; t < NTILES; t += gridDim.x) {
        int I, J;
        decode_tile(t, I, J);
        int Ibase = I * 128, Jbase = J * 128;
        const char* baseI = (const char*)g_C + (size_t)Ibase * 512;
        const char* baseJ = (const char*)g_C + (size_t)Jbase * 512;
        const bool diag = (I == J);

        __syncthreads();   // previous tile's epilogue done with params

        stage_chunk(sbase, baseI, baseJ, 0, tid);
        spAI[tid] = g_A8[Ibase + tid];
        spPI[tid] = g_P8[Ibase + tid];
        spQI[tid] = g_Q[Ibase + tid];
        spLI[tid] = labels[Ibase + tid];
        spAJ[tid] = g_A8[Jbase + tid];
        spPJ[tid] = g_P8[Jbase + tid];
        spQJ[tid] = g_Q[Jbase + tid];
        spLJ[tid] = labels[Jbase + tid];
        asm volatile("cp.async.wait_group 0;" ::: "memory");
        __syncthreads();

        uint32_t acc[4][8][2];
        #pragma unroll
        for (int mi = 0; mi < 4; mi++)
            #pragma unroll
            for (int ni = 0; ni < 8; ni++) { acc[mi][ni][0] = 0u; acc[mi][ni][1] = 0u; }

        #pragma unroll
        for (int c = 0; c < 4; c++) {
            gemm_chunk(csA, csB, lane, warp_m, warp_n, acc);
            __syncthreads();                 // all warps done reading buffer
            if (c < 3) {
                stage_chunk(sbase, baseI, baseJ, c + 1, tid);
                asm volatile("cp.async.wait_group 0;" ::: "memory");
                __syncthreads();
            }
        }

        // fused epilogue: sym/2 = 0.125*Gsum + A8_i + A8_j + P8_i*Q_j + P8_j*Q_i
        // sigmoid(sym) = 0.5 + 0.5*tanh(sym/2)
        #pragma unroll
        for (int mi = 0; mi < 4; mi++) {
            #pragma unroll
            for (int k = 0; k < 2; k++) {
                int r = warp_m * 64 + mi * 16 + (lane >> 2) + k * 8;
                float RA = spAI[r], RP = spPI[r], RQ = spQI[r];
                int   RL = spLI[r];
                #pragma unroll
                for (int ni = 0; ni < 8; ni++) {
                    __half2 hv = *reinterpret_cast<__half2*>(&acc[mi][ni][k]);
                    float2 f = __half22float2(hv);
                    int c0 = warp_n * 64 + ni * 8 + (lane & 3) * 2;
                    #pragma unroll
                    for (int e = 0; e < 2; e++) {
                        int c = c0 + e;
                        float vv = e ? f.y : f.x;
                        float s = fmaf(vv, 0.125f, RA);
                        s += spAJ[c];
                        s = fmaf(RP, spQJ[c], s);
                        s = fmaf(spPJ[c], RQ, s);
                        float sg = fmaf(ftanh(s), 0.5f, 0.5f);
                        bool count = (!diag) || (c > r);
                        bool same  = (RL == spLJ[c]);
                        if (count) {
                            pos += same ? sg : 0.0f;
                            neg += same ? 0.0f : sg;
                        }
                    }
                }
            }
        }
    }

    // ================= final reduce + output by last CTA =================
    #pragma unroll
    for (int off = 16; off; off >>= 1) {
        pos += __shfl_xor_sync(0xffffffffu, pos, off);
        neg += __shfl_xor_sync(0xffffffffu, neg, off);
    }
    __syncthreads();
    if (lane == 0) { red[wid] = pos; red[4 + wid] = neg; }
    __syncthreads();
    if (tid == 0) {
        double P = 0.0, Nn = 0.0;
        #pragma unroll
        for (int w = 0; w < 4; w++) { P += (double)red[w]; Nn += (double)red[4 + w]; }
        atomicAdd(&g_pos, P);
        atomicAdd(&g_neg, Nn);
        __threadfence();
        unsigned d = atomicAdd(&g_done, 1);
        if (d == gridDim.x - 1) {
            double TP = 2.0 * atomicAdd(&g_pos, 0.0);
            double TN = 2.0 * atomicAdd(&g_neg, 0.0);
            const double inv = 1.0 / ((double)NB * (double)NB);
            out[0] = (float)(TP * inv);
            out[1] = (float)(TN * inv);
            out[2] = (float)TP;
            out[3] = (float)TN;
            g_done = 0;
        }
    }
}

// ---------------- launcher ----------------
extern "C" void kernel_launch(void* const* d_in, const int* in_sizes, int n_in,
                              void* d_out, int out_size) {
    (void)in_sizes; (void)n_in; (void)out_size;
    const float* mu     = (const float*)d_in[0];
    const float* var    = (const float*)d_in[1];
    const int*   labels = (const int*)d_in[2];
    float* out = (float*)d_out;

    cudaFuncSetAttribute(mega_kernel, cudaFuncAttributeMaxDynamicSharedMemorySize,
                         SMEM_BYTES);
    int occ = 0, sms = 0, dev = 0;
    cudaGetDevice(&dev);
    cudaOccupancyMaxActiveBlocksPerMultiprocessor(&occ, mega_kernel, 128, SMEM_BYTES);
    cudaDeviceGetAttribute(&sms, cudaDevAttrMultiProcessorCount, dev);
    int grid = occ * sms;
    if (grid > NTILES) grid = NTILES;
    if (grid < 1) grid = 1;

    mega_kernel<<<grid, 128, SMEM_BYTES>>>(mu, var, labels, out);
}

// round 13
// speedup vs baseline: 2.1786x; 1.0011x over previous
#include <cuda_runtime.h>
#include <cuda_fp16.h>
#include <cstdint>

#define NB 4096
#define NT 32               // 32x32 grid of 128x128 tiles
#define NTILES 528          // upper-triangle tiles

// ---------------- device scratch (static: no allocation allowed) ----------------
// C row (256 fp16, 512B): [x | -2m | 1/v | m/v], x = v + m^2
// "D" row = C rotated by 128 cols; 32-wide K-chunk c of D = chunk (c+4)&7 of C.
__device__ __half g_C[(size_t)NB * 256];
__device__ float  g_A8[NB];    // 0.125*a_i - 8
__device__ float  g_P8[NB];    // 0.125*p_i
__device__ float  g_Q[NB];     // 1/(p_i + 1e-8)
__device__ double g_pos, g_neg;
__device__ unsigned g_arrive = 0, g_done = 0;
__device__ volatile unsigned g_release = 0;

static __device__ __forceinline__ uint32_t smem_u32(const void* p) {
    uint32_t a;
    asm("{ .reg .u64 t; cvta.to.shared.u64 t, %1; cvt.u32.u64 %0, t; }" : "=r"(a) : "l"(p));
    return a;
}
static __device__ __forceinline__ float frcp(float x) {
    float r; asm("rcp.approx.f32 %0, %1;" : "=f"(r) : "f"(x)); return r;
}
static __device__ __forceinline__ float ftanh(float x) {
    float r; asm("tanh.approx.f32 %0, %1;" : "=f"(r) : "f"(x)); return r;
}
static __device__ __forceinline__ void cpa16(uint32_t dst, const void* src) {
    asm volatile("cp.async.ca.shared.global [%0], [%1], 16;" :: "r"(dst), "l"(src));
}

// smem: 2 x (A chunk 128x32 fp16 = 8KB + B chunk 128x32 fp16 = 8KB), params, scratch
// 64B-pitch rows, 4 x 16B granules; swizzle granule (c16 + (r>>1)) & 3 ->
// conflict-free for cp.async stores and both ldmatrix fetch shapes.
#define ABUF(b) ((b) * 16384)
#define BBUF(b) ((b) * 16384 + 8192)
#define PAR_OFF 32768
#define RED_OFF 36864
#define SMEM_BYTES 36928

static __device__ __forceinline__ uint32_t swoff(int r, int c16) {
    return (uint32_t)(r * 64 + ((((c16) + (r >> 1)) & 3) << 4));
}

// ---- stage one 32-wide K chunk into buffer b ----
static __device__ __forceinline__ void stage_chunk(
    uint32_t sbase, int b, const char* baseI, const char* baseJ, int c, int tid)
{
    int pa = c * 64, pb = ((c + 4) & 7) * 64;
    #pragma unroll
    for (int p = 0; p < 4; p++) {
        int idx = tid + p * 128, r = idx >> 2, c16 = idx & 3;
        cpa16(sbase + ABUF(b) + swoff(r, c16), baseI + r * 512 + pa + c16 * 16);
    }
    #pragma unroll
    for (int p = 0; p < 4; p++) {
        int idx = tid + p * 128, r = idx >> 2, c16 = idx & 3;
        cpa16(sbase + BBUF(b) + swoff(r, c16), baseJ + r * 512 + pb + c16 * 16);
    }
    asm volatile("cp.async.commit_group;" ::: "memory");
}

// ---- one 32-wide K chunk of the 128x128 GEMM; warp tile 64x64 (2x2 warp grid) ----
static __device__ __forceinline__ void gemm_chunk(
    uint32_t csA, uint32_t csB, int lane, int warp_m, int warp_n,
    uint32_t (&acc)[4][8][2])
{
    #pragma unroll
    for (int s = 0; s < 2; s++) {
        uint32_t af[4][4];
        #pragma unroll
        for (int mi = 0; mi < 4; mi++) {
            int r = warp_m * 64 + mi * 16 + (lane & 15);
            uint32_t addr = csA + swoff(r, 2 * s + (lane >> 4));
            asm volatile("ldmatrix.sync.aligned.m8n8.x4.shared.b16 {%0,%1,%2,%3}, [%4];"
                         : "=r"(af[mi][0]), "=r"(af[mi][1]), "=r"(af[mi][2]), "=r"(af[mi][3])
                         : "r"(addr));
        }
        #pragma unroll
        for (int ni = 0; ni < 8; ni++) {
            int r = warp_n * 64 + ni * 8 + (lane & 7);
            uint32_t addr = csB + swoff(r, 2 * s + ((lane >> 3) & 1));
            uint32_t b0, b1;
            asm volatile("ldmatrix.sync.aligned.m8n8.x2.shared.b16 {%0,%1}, [%2];"
                         : "=r"(b0), "=r"(b1) : "r"(addr));
            #pragma unroll
            for (int mi = 0; mi < 4; mi++) {
                asm volatile(
                    "mma.sync.aligned.m16n8k16.row.col.f16.f16.f16.f16 "
                    "{%0,%1}, {%2,%3,%4,%5}, {%6,%7}, {%0,%1};"
                    : "+r"(acc[mi][ni][0]), "+r"(acc[mi][ni][1])
                    : "r"(af[mi][0]), "r"(af[mi][1]), "r"(af[mi][2]), "r"(af[mi][3]),
                      "r"(b0), "r"(b1));
            }
        }
    }
}

static __device__ __forceinline__ void decode_tile(int ft, int& I, int& J) {
    I = 0;
    while (ft >= NT - I) { ft -= NT - I; I++; }
    J = I + ft;
}

__global__ void __launch_bounds__(128, 4) mega_kernel(
    const float* __restrict__ mu, const float* __restrict__ var,
    const int* __restrict__ labels, float* __restrict__ out)
{
    extern __shared__ char smem[];
    uint32_t sbase = smem_u32(smem);
    int tid = threadIdx.x, lane = tid & 31, wid = tid >> 5;

    // ================= phase 0: prep =================
    for (int row0 = blockIdx.x * 8; row0 < NB; row0 += gridDim.x * 8) {
        int row = row0 + (tid >> 4), l16 = tid & 15;
        float4 m4 = ((const float4*)(mu  + (size_t)row * 64))[l16];
        float4 v4 = ((const float4*)(var + (size_t)row * 64))[l16];
        float m[4] = {m4.x, m4.y, m4.z, m4.w};
        float v[4] = {v4.x, v4.y, v4.z, v4.w};
        float x[4], n2m[4], iv[4], w[4];
        float pv = 1.0f, av = 0.0f;
        #pragma unroll
        for (int d = 0; d < 4; d++) {
            iv[d]  = frcp(v[d]);
            x[d]   = v[d] + m[d] * m[d];
            n2m[d] = -2.0f * m[d];
            w[d]   = m[d] * iv[d];
            pv *= v[d];
            av = fmaf(m[d] * m[d], iv[d], av);
        }
        uint2* crow = (uint2*)(g_C + (size_t)row * 256);
        const float* blocks[4] = {x, n2m, iv, w};
        #pragma unroll
        for (int b = 0; b < 4; b++) {
            const float* s = blocks[b];
            __half2 h2[2] = {__floats2half2_rn(s[0], s[1]), __floats2half2_rn(s[2], s[3])};
            crow[b * 16 + l16] = *(uint2*)h2;
        }
        #pragma unroll
        for (int off = 1; off < 16; off <<= 1) {
            pv *= __shfl_xor_sync(0xffffffffu, pv, off);
            av += __shfl_xor_sync(0xffffffffu, av, off);
        }
        if (l16 == 0) {
            g_A8[row] = 0.125f * av - 8.0f;
            g_P8[row] = 0.125f * pv;
            g_Q[row]  = frcp(pv + 1e-8f);
        }
    }

    // ================= device-wide barrier (all CTAs resident) =================
    __syncthreads();
    if (tid == 0) {
        unsigned target = g_release + 1;
        __threadfence();
        unsigned a = atomicAdd(&g_arrive, 1);
        if (a == gridDim.x - 1) {
            g_arrive = 0;
            g_pos = 0.0; g_neg = 0.0;
            __threadfence();
            atomicAdd((unsigned*)&g_release, 1);
        } else {
            while (g_release < target) __nanosleep(64);
        }
        __threadfence();
    }
    __syncthreads();

    // ================= phase 1: static full-tile loop (single wave) =================
    float* spAI = (float*)(smem + PAR_OFF);
    float* spPI = spAI + 128;
    float* spQI = spPI + 128;
    int*   spLI = (int*)(spQI + 128);
    float* spAJ = (float*)(spLI + 128);
    float* spPJ = spAJ + 128;
    float* spQJ = spPJ + 128;
    int*   spLJ = (int*)(spQJ + 128);
    float* red  = (float*)(smem + RED_OFF);

    int warp_m = wid & 1, warp_n = wid >> 1;
    float pos = 0.0f, neg = 0.0f;

    for (int t = blockIdx.x; t < NTILES; t += gridDim.x) {
        int I, J;
        decode_tile(t, I, J);
        int Ibase = I * 128, Jbase = J * 128;
        const char* baseI = (const char*)g_C + (size_t)Ibase * 512;
        const char* baseJ = (const char*)g_C + (size_t)Jbase * 512;
        const bool diag = (I == J);

        __syncthreads();   // previous tile's epilogue done with params

        // prologue: chunk 0 into buffer 0; params under the cp.async
        stage_chunk(sbase, 0, baseI, baseJ, 0, tid);
        spAI[tid] = g_A8[Ibase + tid];
        spPI[tid] = g_P8[Ibase + tid];
        spQI[tid] = g_Q[Ibase + tid];
        spLI[tid] = labels[Ibase + tid];
        spAJ[tid] = g_A8[Jbase + tid];
        spPJ[tid] = g_P8[Jbase + tid];
        spQJ[tid] = g_Q[Jbase + tid];
        spLJ[tid] = labels[Jbase + tid];

        uint32_t acc[4][8][2];
        #pragma unroll
        for (int mi = 0; mi < 4; mi++)
            #pragma unroll
            for (int ni = 0; ni < 8; ni++) { acc[mi][ni][0] = 0u; acc[mi][ni][1] = 0u; }

        // pipelined chunk loop: wait(c) ; sync ; issue stage(c+1) ; gemm(c)
        #pragma unroll
        for (int c = 0; c < 8; c++) {
            asm volatile("cp.async.wait_group 0;" ::: "memory");
            __syncthreads();
            if (c < 7) stage_chunk(sbase, (c + 1) & 1, baseI, baseJ, c + 1, tid);
            gemm_chunk(sbase + ABUF(c & 1), sbase + BBUF(c & 1),
                       lane, warp_m, warp_n, acc);
        }

        // fused epilogue: sym/2 = 0.125*Gsum + A8_i + A8_j + P8_i*Q_j + P8_j*Q_i
        // sigmoid(sym) = 0.5 + 0.5*tanh(sym/2)
        #pragma unroll
        for (int mi = 0; mi < 4; mi++) {
            #pragma unroll
            for (int k = 0; k < 2; k++) {
                int r = warp_m * 64 + mi * 16 + (lane >> 2) + k * 8;
                float RA = spAI[r], RP = spPI[r], RQ = spQI[r];
                int   RL = spLI[r];
                #pragma unroll
                for (int ni = 0; ni < 8; ni++) {
                    __half2 hv = *reinterpret_cast<__half2*>(&acc[mi][ni][k]);
                    float2 f = __half22float2(hv);
                    int c0 = warp_n * 64 + ni * 8 + (lane & 3) * 2;
                    #pragma unroll
                    for (int e = 0; e < 2; e++) {
                        int c = c0 + e;
                        float vv = e ? f.y : f.x;
                        float s = fmaf(vv, 0.125f, RA);
                        s += spAJ[c];
                        s = fmaf(RP, spQJ[c], s);
                        s = fmaf(spPJ[c], RQ, s);
                        float sg = fmaf(ftanh(s), 0.5f, 0.5f);
                        bool count = (!diag) || (c > r);
                        bool same  = (RL == spLJ[c]);
                        if (count) {
                            pos += same ? sg : 0.0f;
                            neg += same ? 0.0f : sg;
                        }
                    }
                }
            }
        }
    }

    // ================= final reduce + output by last CTA =================
    #pragma unroll
    for (int off = 16; off; off >>= 1) {
        pos += __shfl_xor_sync(0xffffffffu, pos, off);
        neg += __shfl_xor_sync(0xffffffffu, neg, off);
    }
    __syncthreads();
    if (lane == 0) { red[wid] = pos; red[4 + wid] = neg; }
    __syncthreads();
    if (tid == 0) {
        double P = 0.0, Nn = 0.0;
        #pragma unroll
        for (int w = 0; w < 4; w++) { P += (double)red[w]; Nn += (double)red[4 + w]; }
        atomicAdd(&g_pos, P);
        atomicAdd(&g_neg, Nn);
        __threadfence();
        unsigned d = atomicAdd(&g_done, 1);
        if (d == gridDim.x - 1) {
            double TP = 2.0 * atomicAdd(&g_pos, 0.0);
            double TN = 2.0 * atomicAdd(&g_neg, 0.0);
            const double inv = 1.0 / ((double)NB * (double)NB);
            out[0] = (float)(TP * inv);
            out[1] = (float)(TN * inv);
            out[2] = (float)TP;
            out[3] = (float)TN;
            g_done = 0;
        }
    }
}

// ---------------- launcher ----------------
extern "C" void kernel_launch(void* const* d_in, const int* in_sizes, int n_in,
                              void* d_out, int out_size) {
    (void)in_sizes; (void)n_in; (void)out_size;
    const float* mu     = (const float*)d_in[0];
    const float* var    = (const float*)d_in[1];
    const int*   labels = (const int*)d_in[2];
    float* out = (float*)d_out;

    cudaFuncSetAttribute(mega_kernel, cudaFuncAttributeMaxDynamicSharedMemorySize,
                         SMEM_BYTES);
    int occ = 0, sms = 0, dev = 0;
    cudaGetDevice(&dev);
    cudaOccupancyMaxActiveBlocksPerMultiprocessor(&occ, mega_kernel, 128, SMEM_BYTES);
    cudaDeviceGetAttribute(&sms, cudaDevAttrMultiProcessorCount, dev);
    int grid = occ * sms;
    if (grid > NTILES) grid = NTILES;
    if (grid < 1) grid = 1;

    mega_kernel<<<grid, 128, SMEM_BYTES>>>(mu, var, labels, out);
}

// round 14
// speedup vs baseline: 2.3613x; 1.0838x over previous
#include <cuda_runtime.h>
#include <cstdint>

#define NB 4096
#define NT 32               // 32x32 grid of 128x128 tiles
#define NITEMS 1056         // two 128x64 half-tiles per upper-triangle tile
#define FMA_NONE 0

// ---------------- device scratch (static: no allocation allowed) ----------------
// C row (256 e4m3 bytes): [x | -2m | 1/v | m/v] (64B each), x = v + m^2
// "D" row = C rotated by 128 bytes; 128B-chunk c of D = chunk 1-c of C.
__device__ uint8_t g_C[(size_t)NB * 256];
__device__ float  g_A8[NB];    // 0.125*a_i - 8
__device__ float  g_P8[NB];    // 0.125*p_i
__device__ float  g_Q[NB];     // 1/(p_i + 1e-8)
__device__ double g_pos, g_neg;
__device__ unsigned g_arrive = 0, g_done = 0, g_ticket = 0;
__device__ volatile unsigned g_release = 0;

static __device__ __forceinline__ uint32_t smem_u32(const void* p) {
    uint32_t a;
    asm("{ .reg .u64 t; cvta.to.shared.u64 t, %1; cvt.u32.u64 %0, t; }" : "=r"(a) : "l"(p));
    return a;
}
static __device__ __forceinline__ float frcp(float x) {
    float r; asm("rcp.approx.f32 %0, %1;" : "=f"(r) : "f"(x)); return r;
}
static __device__ __forceinline__ float ftanh(float x) {
    float r; asm("tanh.approx.f32 %0, %1;" : "=f"(r) : "f"(x)); return r;
}
static __device__ __forceinline__ void cpa16(uint32_t dst, const void* src) {
    asm volatile("cp.async.ca.shared.global [%0], [%1], 16;" :: "r"(dst), "l"(src));
}
// pack 4 floats -> 4 e4m3 bytes (s0 in low byte)
static __device__ __forceinline__ uint32_t pack_e4m3(float s0, float s1, float s2, float s3) {
    uint32_t r;
    asm("{ .reg .b16 a, b;\n\t"
        "cvt.rn.satfinite.e4m3x2.f32 a, %2, %1;\n\t"
        "cvt.rn.satfinite.e4m3x2.f32 b, %4, %3;\n\t"
        "mov.b32 %0, {a, b}; }"
        : "=r"(r) : "f"(s0), "f"(s1), "f"(s2), "f"(s3));
    return r;
}

// smem: A chunk 128 rows x 128B (16KB, XOR-swizzled 16B granules),
//       B chunk 64 rows x 128B (8KB), params 3KB, scratch
#define AS_OFF 0
#define BS_OFF 16384
#define PAR_OFF 24576
#define RED_OFF 27648
#define SMEM_BYTES 27712

static __device__ __forceinline__ uint32_t swoff(int r, int g) {
    return (uint32_t)(r * 128 + (((g) ^ (r & 7)) << 4));
}

// ---- stage one 128B K chunk: A = C(I) chunk c, B = C(J) chunk 1-c ----
static __device__ __forceinline__ void stage_chunk(
    uint32_t sbase, const char* baseI, const char* baseJ, int c, int tid)
{
    int pa = c * 128, pb = 128 - c * 128;
    #pragma unroll
    for (int p = 0; p < 8; p++) {
        int idx = tid + p * 128, r = idx >> 3, g = idx & 7;
        cpa16(sbase + AS_OFF + swoff(r, g), baseI + r * 256 + pa + g * 16);
    }
    #pragma unroll
    for (int p = 0; p < 4; p++) {
        int idx = tid + p * 128, r = idx >> 3, g = idx & 7;
        cpa16(sbase + BS_OFF + swoff(r, g), baseJ + r * 256 + pb + g * 16);
    }
    asm volatile("cp.async.commit_group;" ::: "memory");
}

// ---- one 128B K chunk of the 128x64 FP8 GEMM; warp tile 64x32 (2x2 warp grid) ----
static __device__ __forceinline__ void gemm_chunk(
    uint32_t csA, uint32_t csB, int lane, int warp_m, int warp_n,
    float (&acc)[4][4][4])
{
    #pragma unroll
    for (int s = 0; s < 4; s++) {
        // A: 4 x LDSM.x4, each 16 rows x k32 (granules 2s, 2s+1)
        uint32_t af[4][4];
        #pragma unroll
        for (int mi = 0; mi < 4; mi++) {
            int r = warp_m * 64 + mi * 16 + (lane & 15);
            uint32_t addr = csA + swoff(r, 2 * s + (lane >> 4));
            asm volatile("ldmatrix.sync.aligned.m8n8.x4.shared.b16 {%0,%1,%2,%3}, [%4];"
                         : "=r"(af[mi][0]), "=r"(af[mi][1]), "=r"(af[mi][2]), "=r"(af[mi][3])
                         : "r"(addr));
        }
        // B: 2 x LDSM.x4 -> 4 n8-blocks; regs {b0(blk0), b0(blk1), b1(blk0), b1(blk1)}
        uint32_t bf[2][4];
        #pragma unroll
        for (int nj = 0; nj < 2; nj++) {
            int r = warp_n * 32 + nj * 16 + (lane & 15);
            uint32_t addr = csB + swoff(r, 2 * s + (lane >> 4));
            asm volatile("ldmatrix.sync.aligned.m8n8.x4.shared.b16 {%0,%1,%2,%3}, [%4];"
                         : "=r"(bf[nj][0]), "=r"(bf[nj][1]), "=r"(bf[nj][2]), "=r"(bf[nj][3])
                         : "r"(addr));
        }
        #pragma unroll
        for (int ni = 0; ni < 4; ni++) {
            uint32_t b0 = bf[ni >> 1][(ni & 1)];
            uint32_t b1 = bf[ni >> 1][(ni & 1) + 2];
            #pragma unroll
            for (int mi = 0; mi < 4; mi++) {
                asm volatile(
                    "mma.sync.aligned.m16n8k32.row.col.f32.e4m3.e4m3.f32 "
                    "{%0,%1,%2,%3}, {%4,%5,%6,%7}, {%8,%9}, {%0,%1,%2,%3};"
                    : "+f"(acc[mi][ni][0]), "+f"(acc[mi][ni][1]),
                      "+f"(acc[mi][ni][2]), "+f"(acc[mi][ni][3])
                    : "r"(af[mi][0]), "r"(af[mi][1]), "r"(af[mi][2]), "r"(af[mi][3]),
                      "r"(b0), "r"(b1));
            }
        }
    }
}

static __device__ __forceinline__ void decode_item(unsigned t, int& I, int& J, int& half) {
    int ft = (int)(t >> 1); half = (int)(t & 1); I = 0;
    while (ft >= NT - I) { ft -= NT - I; I++; }
    J = I + ft;
}

__global__ void __launch_bounds__(128, 4) mega_kernel(
    const float* __restrict__ mu, const float* __restrict__ var,
    const int* __restrict__ labels, float* __restrict__ out)
{
    extern __shared__ char smem[];
    uint32_t sbase = smem_u32(smem);
    int tid = threadIdx.x, lane = tid & 31, wid = tid >> 5;

    // ================= phase 0: prep =================
    for (int row0 = blockIdx.x * 8; row0 < NB; row0 += gridDim.x * 8) {
        int row = row0 + (tid >> 4), l16 = tid & 15;
        float4 m4 = ((const float4*)(mu  + (size_t)row * 64))[l16];
        float4 v4 = ((const float4*)(var + (size_t)row * 64))[l16];
        float m[4] = {m4.x, m4.y, m4.z, m4.w};
        float v[4] = {v4.x, v4.y, v4.z, v4.w};
        float x[4], n2m[4], iv[4], w[4];
        float pv = 1.0f, av = 0.0f;
        #pragma unroll
        for (int d = 0; d < 4; d++) {
            iv[d]  = frcp(v[d]);
            x[d]   = v[d] + m[d] * m[d];
            n2m[d] = -2.0f * m[d];
            w[d]   = m[d] * iv[d];
            pv *= v[d];
            av = fmaf(m[d] * m[d], iv[d], av);
        }
        uint32_t* crow = (uint32_t*)(g_C + (size_t)row * 256);   // 64 u32 per row
        crow[0 * 16 + l16] = pack_e4m3(x[0], x[1], x[2], x[3]);
        crow[1 * 16 + l16] = pack_e4m3(n2m[0], n2m[1], n2m[2], n2m[3]);
        crow[2 * 16 + l16] = pack_e4m3(iv[0], iv[1], iv[2], iv[3]);
        crow[3 * 16 + l16] = pack_e4m3(w[0], w[1], w[2], w[3]);
        #pragma unroll
        for (int off = 1; off < 16; off <<= 1) {
            pv *= __shfl_xor_sync(0xffffffffu, pv, off);
            av += __shfl_xor_sync(0xffffffffu, av, off);
        }
        if (l16 == 0) {
            g_A8[row] = 0.125f * av - 8.0f;
            g_P8[row] = 0.125f * pv;
            g_Q[row]  = frcp(pv + 1e-8f);
        }
    }

    // ================= device-wide barrier (all CTAs resident) =================
    __syncthreads();
    if (tid == 0) {
        unsigned target = g_release + 1;
        __threadfence();
        unsigned a = atomicAdd(&g_arrive, 1);
        if (a == gridDim.x - 1) {
            g_arrive = 0;
            g_pos = 0.0; g_neg = 0.0;
            g_ticket = gridDim.x;
            __threadfence();
            atomicAdd((unsigned*)&g_release, 1);
        } else {
            while (g_release < target) __nanosleep(64);
        }
        __threadfence();
    }
    __syncthreads();

    // ================= phase 1: half-tile (128x64) ticketed loop =================
    float* spAI = (float*)(smem + PAR_OFF);
    float* spPI = spAI + 128;
    float* spQI = spPI + 128;
    int*   spLI = (int*)(spQI + 128);
    float* spAJ = (float*)(spLI + 128);   // 64 entries
    float* spPJ = spAJ + 64;
    float* spQJ = spPJ + 64;
    int*   spLJ = (int*)(spQJ + 64);
    float* red  = (float*)(smem + RED_OFF);
    unsigned* tick_s = (unsigned*)(red + 8);

    uint32_t csA = sbase + AS_OFF, csB = sbase + BS_OFF;
    int warp_m = wid & 1, warp_n = wid >> 1;
    float pos = 0.0f, neg = 0.0f;
    unsigned t = blockIdx.x;

    while (t < NITEMS) {
        int I, J, half;
        decode_item(t, I, J, half);
        int Ibase = I * 128, Jbase = J * 128 + half * 64;
        const char* baseI = (const char*)g_C + (size_t)Ibase * 256;
        const char* baseJ = (const char*)g_C + (size_t)Jbase * 256;
        const bool diag = (I == J);

        __syncthreads();   // previous item's epilogue done with smem

        stage_chunk(sbase, baseI, baseJ, 0, tid);
        spAI[tid] = g_A8[Ibase + tid];
        spPI[tid] = g_P8[Ibase + tid];
        spQI[tid] = g_Q[Ibase + tid];
        spLI[tid] = labels[Ibase + tid];
        if (tid < 64) {
            spAJ[tid] = g_A8[Jbase + tid];
            spPJ[tid] = g_P8[Jbase + tid];
            spQJ[tid] = g_Q[Jbase + tid];
            spLJ[tid] = labels[Jbase + tid];
        }
        asm volatile("cp.async.wait_group 0;" ::: "memory");
        __syncthreads();

        float acc[4][4][4];
        #pragma unroll
        for (int mi = 0; mi < 4; mi++)
            #pragma unroll
            for (int ni = 0; ni < 4; ni++)
                #pragma unroll
                for (int e = 0; e < 4; e++) acc[mi][ni][e] = 0.0f;

        gemm_chunk(csA, csB, lane, warp_m, warp_n, acc);

        __syncthreads();
        stage_chunk(sbase, baseI, baseJ, 1, tid);
        if (tid == 0) *tick_s = atomicAdd(&g_ticket, 1);
        asm volatile("cp.async.wait_group 0;" ::: "memory");
        __syncthreads();

        gemm_chunk(csA, csB, lane, warp_m, warp_n, acc);

        unsigned nt = *tick_s;

        // fused epilogue: sym/2 = 0.125*Gsum + A8_i + A8_j + P8_i*Q_j + P8_j*Q_i
        // sigmoid(sym) = 0.5 + 0.5*tanh(sym/2)
        #pragma unroll
        for (int mi = 0; mi < 4; mi++) {
            #pragma unroll
            for (int k = 0; k < 2; k++) {
                int r = warp_m * 64 + mi * 16 + (lane >> 2) + k * 8;
                float RA = spAI[r], RP = spPI[r], RQ = spQI[r];
                int   RL = spLI[r];
                #pragma unroll
                for (int ni = 0; ni < 4; ni++) {
                    int c0 = warp_n * 32 + ni * 8 + (lane & 3) * 2;
                    #pragma unroll
                    for (int e = 0; e < 2; e++) {
                        int c = c0 + e;
                        float vv = acc[mi][ni][k * 2 + e];
                        float s = fmaf(vv, 0.125f, RA);
                        s += spAJ[c];
                        s = fmaf(RP, spQJ[c], s);
                        s = fmaf(spPJ[c], RQ, s);
                        float sg = fmaf(ftanh(s), 0.5f, 0.5f);
                        bool count = (!diag) || (half * 64 + c > r);
                        bool same  = (RL == spLJ[c]);
                        if (count) {
                            pos += same ? sg : 0.0f;
                            neg += same ? 0.0f : sg;
                        }
                    }
                }
            }
        }

        t = nt;
    }

    // ================= final reduce + output by last CTA =================
    #pragma unroll
    for (int off = 16; off; off >>= 1) {
        pos += __shfl_xor_sync(0xffffffffu, pos, off);
        neg += __shfl_xor_sync(0xffffffffu, neg, off);
    }
    __syncthreads();
    if (lane == 0) { red[wid] = pos; red[4 + wid] = neg; }
    __syncthreads();
    if (tid == 0) {
        double P = 0.0, Nn = 0.0;
        #pragma unroll
        for (int w = 0; w < 4; w++) { P += (double)red[w]; Nn += (double)red[4 + w]; }
        atomicAdd(&g_pos, P);
        atomicAdd(&g_neg, Nn);
        __threadfence();
        unsigned d = atomicAdd(&g_done, 1);
        if (d == gridDim.x - 1) {
            double TP = 2.0 * atomicAdd(&g_pos, 0.0);
            double TN = 2.0 * atomicAdd(&g_neg, 0.0);
            const double inv = 1.0 / ((double)NB * (double)NB);
            out[0] = (float)(TP * inv);
            out[1] = (float)(TN * inv);
            out[2] = (float)TP;
            out[3] = (float)TN;
            g_done = 0;
        }
    }
}

// ---------------- launcher ----------------
extern "C" void kernel_launch(void* const* d_in, const int* in_sizes, int n_in,
                              void* d_out, int out_size) {
    (void)in_sizes; (void)n_in; (void)out_size;
    const float* mu     = (const float*)d_in[0];
    const float* var    = (const float*)d_in[1];
    const int*   labels = (const int*)d_in[2];
    float* out = (float*)d_out;

    cudaFuncSetAttribute(mega_kernel, cudaFuncAttributeMaxDynamicSharedMemorySize,
                         SMEM_BYTES);
    int occ = 0, sms = 0, dev = 0;
    cudaGetDevice(&dev);
    cudaOccupancyMaxActiveBlocksPerMultiprocessor(&occ, mega_kernel, 128, SMEM_BYTES);
    cudaDeviceGetAttribute(&sms, cudaDevAttrMultiProcessorCount, dev);
    int grid = occ * sms;
    if (grid > NITEMS) grid = NITEMS;
    if (grid < 1) grid = 1;

    mega_kernel<<<grid, 128, SMEM_BYTES>>>(mu, var, labels, out);
}